// round 16
// baseline (speedup 1.0000x reference)
#include <cuda_runtime.h>
#include <cuda_fp16.h>
#include <cstdint>

// ============================================================================
// CISSVAE forward on GB300 — R16: R11 mainloop (64x128 tiles, 128thr,
// 4 CTAs/SM, fp16 m16n8k16, BK=32, 3-stage cp.async) wrapped in a
// grid-stride work loop (592 persistent CTAs per layer launch) to remove
// wave-quantization tails. Scatter fused into the prepass kernel.
// Rows counting-sorted by cluster -> per-cluster layers are dense segments.
// ============================================================================

#define BB 16384
#define NC 8
#define MAXT 264          // 64-row tiles: BB/64 + NC
#define PGRID 592         // 4 CTAs/SM x 148 SMs

__device__ __half g_bufA[BB * 1024];
__device__ __half g_bufB[BB * 1024];
__device__ __half g_xh[BB * 512];
__device__ __half g_wh[13500416];
__device__ __half g_whz[32768];
__device__ int    g_perm[BB];
__device__ int    g_cursor[NC];
__device__ int4   g_tiles[MAXT];
__device__ int    g_numTiles;

#define O_EW0   0
#define O_EWU   524288
#define O_EW2   4718592
#define O_DWU0  4849664
#define O_DW1   4980736
#define O_DWU2  5111808
#define O_FW    9306112

// ---------------------------------------------------------------------------
__global__ void k_setup(const int* __restrict__ labels) {
    __shared__ int cnt[NC];
    int t = threadIdx.x;
    if (t < NC) cnt[t] = 0;
    __syncthreads();
    int loc[NC];
#pragma unroll
    for (int c = 0; c < NC; c++) loc[c] = 0;
    for (int i = t; i < BB; i += blockDim.x) {
        int v = labels[i];
#pragma unroll
        for (int c = 0; c < NC; c++) loc[c] += (v == c);
    }
#pragma unroll
    for (int c = 0; c < NC; c++)
        if (loc[c]) atomicAdd(&cnt[c], loc[c]);
    __syncthreads();
    if (t == 0) {
        int start = 0, nt = 0;
        for (int c = 0; c < NC; c++) {
            g_cursor[c] = start;
            int n = cnt[c];
            for (int off = 0; off < n; off += 64) {
                g_tiles[nt] = make_int4(start + off, min(64, n - off), c, 0);
                nt++;
            }
            start += n;
        }
        g_numTiles = nt;
    }
}

// ---------------------------------------------------------------------------
// Fused kernel: blocks [0,64) scatter rows by cluster; blocks [64, ...)
// do 8 fp32->fp16 conversion jobs + mu/lv interleave job.
// ---------------------------------------------------------------------------
#define NJOBS 8
#define SCATB 64
struct CvtJobs {
    const float* s[NJOBS];
    __half* d[NJOBS];
    int n4[NJOBS];
    int bstart[NJOBS + 2];       // offsets AFTER the SCATB scatter blocks
    const float* zmu; const float* zlv; __half* zo;
    const int* labels;
};

__global__ void __launch_bounds__(256)
k_prep(CvtJobs J) {
    int b = blockIdx.x;
    if (b < SCATB) {
        int i = b * 256 + threadIdx.x;
        if (i < BB) {
            int p = atomicAdd(&g_cursor[J.labels[i]], 1);
            g_perm[p] = i;
        }
        return;
    }
    b -= SCATB;
    if (b >= J.bstart[NJOBS]) {
        int lb = b - J.bstart[NJOBS];
#pragma unroll
        for (int it = 0; it < 4; it++) {
            int idx = lb * 1024 + it * 256 + threadIdx.x;
            if (idx < 4096) {
                float4 m = ((const float4*)J.zmu)[idx];
                float4 l = ((const float4*)J.zlv)[idx];
                int i0 = idx * 4;
                int k = i0 >> 6, j0 = i0 & 63;
                __half2* o = (__half2*)(J.zo + (size_t)k * 128 + 2 * j0);
                o[0] = __floats2half2_rn(m.x, l.x);
                o[1] = __floats2half2_rn(m.y, l.y);
                o[2] = __floats2half2_rn(m.z, l.z);
                o[3] = __floats2half2_rn(m.w, l.w);
            }
        }
        return;
    }
    int j = 0;
#pragma unroll
    for (int q = 1; q < NJOBS; q++)
        if (b >= J.bstart[q]) j = q;
    int lb = b - J.bstart[j];
    const float4* src = (const float4*)J.s[j];
    __half2* dst = (__half2*)J.d[j];
    int n4 = J.n4[j];
#pragma unroll
    for (int it = 0; it < 4; it++) {
        int idx = lb * 1024 + it * 256 + threadIdx.x;
        if (idx < n4) {
            float4 v = src[idx];
            dst[idx * 2 + 0] = __floats2half2_rn(v.x, v.y);
            dst[idx * 2 + 1] = __floats2half2_rn(v.z, v.w);
        }
    }
}

// ---------------------------------------------------------------------------
__device__ __forceinline__ void mma16(float* c, const uint32_t* a, const uint32_t* b) {
    asm volatile(
        "mma.sync.aligned.m16n8k16.row.col.f32.f16.f16.f32 "
        "{%0,%1,%2,%3}, {%4,%5,%6,%7}, {%8,%9}, {%0,%1,%2,%3};\n"
        : "+f"(c[0]), "+f"(c[1]), "+f"(c[2]), "+f"(c[3])
        : "r"(a[0]), "r"(a[1]), "r"(a[2]), "r"(a[3]), "r"(b[0]), "r"(b[1]));
}
__device__ __forceinline__ void ldsm4(uint32_t* r, uint32_t saddr) {
    asm volatile("ldmatrix.sync.aligned.m8n8.x4.shared.b16 {%0,%1,%2,%3}, [%4];"
                 : "=r"(r[0]), "=r"(r[1]), "=r"(r[2]), "=r"(r[3]) : "r"(saddr));
}
__device__ __forceinline__ void ldsm4t(uint32_t* r, uint32_t saddr) {
    asm volatile("ldmatrix.sync.aligned.m8n8.x4.trans.shared.b16 {%0,%1,%2,%3}, [%4];"
                 : "=r"(r[0]), "=r"(r[1]), "=r"(r[2]), "=r"(r[3]) : "r"(saddr));
}
__device__ __forceinline__ void cp16(uint32_t saddr, const void* g, int szbytes) {
    asm volatile("cp.async.cg.shared.global [%0], [%1], 16, %2;\n"
                 :: "r"(saddr), "l"(g), "r"(szbytes));
}
#define CP_COMMIT() asm volatile("cp.async.commit_group;\n")
#define CP_WAIT0()  asm volatile("cp.async.wait_group 0;\n")
#define CP_WAIT1()  asm volatile("cp.async.wait_group 1;\n")

// smem: 3 stages; A stage 64 rows x 80B, B stage 32 rows x 272B
#define A_BUF 5120
#define B_BUF 8704
#define SB0   15360
#define SMEM_TOTAL 41472

// ---------------------------------------------------------------------------
// MODE 0: bias+relu -> fp16 Out.
// MODE 2: interleaved mu/lv -> z = mu + exp(0.5 lv)*eps -> fp16 Out [.,64].
// MODE 3: bias only -> fp32 scatter to original rows.
// Tile 64x128x32, 4 warps (1M x 4N). Grid-stride over (tile, chunk) units.
// ---------------------------------------------------------------------------
template <int MODE, int K, int N, int NCHUNK>
__global__ void __launch_bounds__(128, 4)
k_hgemm(const __half* __restrict__ A, const __half* __restrict__ W,
        const float* __restrict__ bias, const float* __restrict__ bias2,
        const float* __restrict__ epsp, void* __restrict__ OutV,
        int unsharedF, int permAF) {
    __shared__ __align__(16) __half smem_[SMEM_TOTAL / 2];
    uint32_t smb = (uint32_t)__cvta_generic_to_shared(smem_);

    int tid = threadIdx.x;
    int warp = tid >> 5, lane = tid & 31;
    int wn = warp;
    int g = lane >> 2, tg = lane & 3;

    int nt = g_numTiles;
    int total = nt * NCHUNK;

    // tile-invariant fragment bases
    uint32_t aF = smb + (uint32_t)((lane & 15) * 80 + ((lane >> 4) << 4));
    uint32_t bF = smb + SB0 +
        (uint32_t)((((lane >> 3) & 1) * 8 + (lane & 7)) * 272 + (wn * 32 + ((lane >> 4) << 3)) * 2);

    bool first = true;
    for (int w = blockIdx.x; w < total; w += PGRID) {
        int tileIdx = w % nt;
        int chunk = w / nt;
        int nb = chunk * 128;

        if (!first) __syncthreads();   // smem from previous tile fully consumed
        first = false;

        int4 td = g_tiles[tileIdx];
        int rowStart = td.x, rows = td.y, cl = td.z;
        const __half* Wp = W + (unsharedF ? (size_t)cl * K * N : 0);
        const float* bp = bias + (unsharedF ? (size_t)cl * N : 0);

        // per-tile staging coords
        uint32_t aDst[2]; const __half* aSrc[2]; int aSz[2];
        uint32_t bDst[4]; const __half* bSrc[4];
#pragma unroll
        for (int i = 0; i < 2; i++) {
            int idx = tid + i * 128;
            int r = idx >> 2, ch = idx & 3;
            int ok = (r < rows);
            aSz[i] = ok ? 16 : 0;
            int ar = ok ? (permAF ? g_perm[rowStart + r] : rowStart + r) : 0;
            aDst[i] = smb + r * 80 + ch * 16;
            aSrc[i] = A + (size_t)ar * K + ch * 8;
        }
#pragma unroll
        for (int i = 0; i < 4; i++) {
            int idx = tid + i * 128;
            int kr = idx >> 4, cq = (idx & 15) << 3;
            bDst[i] = smb + SB0 + kr * 272 + cq * 2;
            bSrc[i] = Wp + (size_t)kr * N + nb + cq;
        }

        auto loadTile = [&](int blk, int s) {
            int ko = blk * 32;
#pragma unroll
            for (int i = 0; i < 2; i++) cp16(aDst[i] + s * A_BUF, aSrc[i] + ko, aSz[i]);
#pragma unroll
            for (int i = 0; i < 4; i++) cp16(bDst[i] + s * B_BUF, bSrc[i] + (size_t)ko * N, 16);
            CP_COMMIT();
        };

        float acc[4][4][4];
#pragma unroll
        for (int a = 0; a < 4; a++)
#pragma unroll
            for (int b = 0; b < 4; b++)
#pragma unroll
                for (int d = 0; d < 4; d++) acc[a][b][d] = 0.f;

        const int nk = K / 32;
        loadTile(0, 0);
        if (nk > 1) loadTile(1, 1);

        for (int i = 0; i < nk; i++) {
            int s = i % 3;
            if (i + 1 < nk) { CP_WAIT1(); } else { CP_WAIT0(); }
            __syncthreads();
            if (i + 2 < nk) loadTile(i + 2, (i + 2) % 3);

            uint32_t aB = aF + s * A_BUF, bB = bF + s * B_BUF;
#pragma unroll
            for (int ks = 0; ks < 2; ks++) {
                uint32_t af[4][4], bfr[2][4];
#pragma unroll
                for (int mt = 0; mt < 4; mt++)
                    ldsm4(af[mt], aB + mt * (16 * 80) + ks * 32);
#pragma unroll
                for (int np = 0; np < 2; np++)
                    ldsm4t(bfr[np], bB + ks * (16 * 272) + np * 32);
#pragma unroll
                for (int mt = 0; mt < 4; mt++)
#pragma unroll
                    for (int nt2 = 0; nt2 < 4; nt2++)
                        mma16(acc[mt][nt2], af[mt], &bfr[nt2 >> 1][(nt2 & 1) * 2]);
            }
        }

        // epilogue
#pragma unroll
        for (int mt = 0; mt < 4; mt++) {
#pragma unroll
            for (int nt2 = 0; nt2 < 4; nt2++) {
                int col = nb + wn * 32 + nt2 * 8 + 2 * tg;
                float bv0, bv1;
                if (MODE == 2) { int j = col >> 1; bv0 = bias[j]; bv1 = bias2[j]; }
                else { bv0 = bp[col]; bv1 = bp[col + 1]; }
#pragma unroll
                for (int h = 0; h < 2; h++) {
                    int lr = mt * 16 + g + h * 8;
                    if (lr < rows) {
                        int grow = rowStart + lr;
                        float v0 = acc[mt][nt2][2 * h + 0] + bv0;
                        float v1 = acc[mt][nt2][2 * h + 1] + bv1;
                        if (MODE == 0) {
                            __half2 hv = __floats2half2_rn(fmaxf(v0, 0.f), fmaxf(v1, 0.f));
                            *(__half2*)((__half*)OutV + (size_t)grow * N + col) = hv;
                        } else if (MODE == 2) {
                            int j = col >> 1;
                            int orig = g_perm[grow];
                            float e = epsp[(size_t)orig * 64 + j];
                            ((__half*)OutV)[(size_t)grow * 64 + j] =
                                __float2half(v0 + expf(0.5f * v1) * e);
                        } else {
                            int orig = g_perm[grow];
                            *(float2*)((float*)OutV + (size_t)orig * N + col) = make_float2(v0, v1);
                        }
                    }
                }
            }
        }
    }
}

// ---------------------------------------------------------------------------
extern "C" void kernel_launch(void* const* d_in, const int* in_sizes, int n_in,
                              void* d_out, int out_size) {
    const float* x      = (const float*)d_in[0];
    const int*   lbl    = (const int*)d_in[1];
    const float* eps    = (const float*)d_in[2];
    const float* enc_W0 = (const float*)d_in[3];
    const float* enc_b0 = (const float*)d_in[4];
    const float* enc_Wu = (const float*)d_in[5];
    const float* enc_bu = (const float*)d_in[6];
    const float* enc_W2 = (const float*)d_in[7];
    const float* enc_b2 = (const float*)d_in[8];
    const float* mu_W   = (const float*)d_in[9];
    const float* mu_b   = (const float*)d_in[10];
    const float* lv_W   = (const float*)d_in[11];
    const float* lv_b   = (const float*)d_in[12];
    const float* dWu0   = (const float*)d_in[13];
    const float* dbu0   = (const float*)d_in[14];
    const float* dW1    = (const float*)d_in[15];
    const float* db1    = (const float*)d_in[16];
    const float* dWu2   = (const float*)d_in[17];
    const float* dbu2   = (const float*)d_in[18];
    const float* fW     = (const float*)d_in[19];
    const float* fb     = (const float*)d_in[20];
    float* out = (float*)d_out;

    __half *bufA, *bufB, *xh, *wh, *whz;
    cudaGetSymbolAddress((void**)&bufA, g_bufA);
    cudaGetSymbolAddress((void**)&bufB, g_bufB);
    cudaGetSymbolAddress((void**)&xh,   g_xh);
    cudaGetSymbolAddress((void**)&wh,   g_wh);
    cudaGetSymbolAddress((void**)&whz,  g_whz);

    k_setup<<<1, 256>>>(lbl);

    // fused scatter + prepass (fp32->fp16 of x + 7 weights + z interleave)
    {
        CvtJobs J;
        const float* srcs[NJOBS] = {x, enc_W0, enc_Wu, enc_W2, dWu0, dW1, dWu2, fW};
        __half* dsts[NJOBS] = {xh, wh + O_EW0, wh + O_EWU, wh + O_EW2,
                               wh + O_DWU0, wh + O_DW1, wh + O_DWU2, wh + O_FW};
        int n4s[NJOBS] = {BB * 512 / 4, 524288 / 4, 4194304 / 4, 131072 / 4,
                          131072 / 4, 131072 / 4, 4194304 / 4, 4194304 / 4};
        int bs = 0;
        for (int j = 0; j < NJOBS; j++) {
            J.s[j] = srcs[j]; J.d[j] = dsts[j]; J.n4[j] = n4s[j];
            J.bstart[j] = bs;
            bs += (n4s[j] + 1023) / 1024;
        }
        J.bstart[NJOBS] = bs;
        bs += 4;
        J.bstart[NJOBS + 1] = bs;
        J.zmu = mu_W; J.zlv = lv_W; J.zo = whz;
        J.labels = lbl;
        k_prep<<<bs + SCATB, 256>>>(J);
    }

    // L1: xh(perm) @ enc_W0 [512->1024] relu
    k_hgemm<0, 512, 1024, 8><<<PGRID, 128>>>(xh, wh + O_EW0, enc_b0, nullptr, nullptr, bufA, 0, 1);
    // L2: H1 @ enc_Wu[c] [1024->512] relu
    k_hgemm<0, 1024, 512, 4><<<PGRID, 128>>>(bufA, wh + O_EWU, enc_bu, nullptr, nullptr, bufB, 1, 0);
    // L3: H2 @ enc_W2 [512->256] relu
    k_hgemm<0, 512, 256, 2><<<PGRID, 128>>>(bufB, wh + O_EW2, enc_b2, nullptr, nullptr, bufA, 0, 0);
    // L4: mu/lv heads + reparameterize -> Z (fp16, 64 wide)
    k_hgemm<2, 256, 128, 1><<<PGRID, 128>>>(bufA, whz, mu_b, lv_b, eps, bufB, 0, 0);
    // L5: Z @ dec_Wu0[c] [64->256] relu
    k_hgemm<0, 64, 256, 2><<<PGRID, 128>>>(bufB, wh + O_DWU0, dbu0, nullptr, nullptr, bufA, 1, 0);
    // L6: D1 @ dec_W1 [256->512] relu
    k_hgemm<0, 256, 512, 4><<<PGRID, 128>>>(bufA, wh + O_DW1, db1, nullptr, nullptr, bufB, 0, 0);
    // L7: D2 @ dec_Wu2[c] [512->1024] relu
    k_hgemm<0, 512, 1024, 8><<<PGRID, 128>>>(bufB, wh + O_DWU2, dbu2, nullptr, nullptr, bufA, 1, 0);
    // L8: D3 @ fin_W[c] [1024->512], scatter to original rows (fp32 out)
    k_hgemm<3, 1024, 512, 4><<<PGRID, 128>>>(bufA, wh + O_FW, fb, nullptr, nullptr, out, 1, 0);
}

// round 17
// speedup vs baseline: 1.0507x; 1.0507x over previous
#include <cuda_runtime.h>
#include <cuda_fp16.h>
#include <cstdint>

// ============================================================================
// CISSVAE forward on GB300 — R17: champion R11 GEMM path restored verbatim
// (64x128 tiles, 128 thr, 4 CTAs/SM, fp16 m16n8k16, BK=32, 3-stage cp.async,
// one barrier per k-block) + scatter fused into the single prepass launch.
// Rows counting-sorted by cluster -> per-cluster layers are dense segments.
// ============================================================================

#define BB 16384
#define NC 8
#define MAXT 264          // 64-row tiles: BB/64 + NC

__device__ __half g_bufA[BB * 1024];
__device__ __half g_bufB[BB * 1024];
__device__ __half g_xh[BB * 512];
__device__ __half g_wh[13500416];
__device__ __half g_whz[32768];     // interleaved mu/lv weights [256][128]
__device__ int    g_perm[BB];
__device__ int    g_cursor[NC];
__device__ int4   g_tiles[MAXT];
__device__ int    g_numTiles;

#define O_EW0   0
#define O_EWU   524288
#define O_EW2   4718592
#define O_DWU0  4849664
#define O_DW1   4980736
#define O_DWU2  5111808
#define O_FW    9306112

// ---------------------------------------------------------------------------
__global__ void k_setup(const int* __restrict__ labels) {
    __shared__ int cnt[NC];
    int t = threadIdx.x;
    if (t < NC) cnt[t] = 0;
    __syncthreads();
    int loc[NC];
#pragma unroll
    for (int c = 0; c < NC; c++) loc[c] = 0;
    for (int i = t; i < BB; i += blockDim.x) {
        int v = labels[i];
#pragma unroll
        for (int c = 0; c < NC; c++) loc[c] += (v == c);
    }
#pragma unroll
    for (int c = 0; c < NC; c++)
        if (loc[c]) atomicAdd(&cnt[c], loc[c]);
    __syncthreads();
    if (t == 0) {
        int start = 0, nt = 0;
        for (int c = 0; c < NC; c++) {
            g_cursor[c] = start;
            int n = cnt[c];
            for (int off = 0; off < n; off += 64) {
                g_tiles[nt] = make_int4(start + off, min(64, n - off), c, 0);
                nt++;
            }
            start += n;
        }
        g_numTiles = nt;
    }
}

// ---------------------------------------------------------------------------
// Fused prep: blocks [0,64) scatter rows by cluster; remaining blocks run
// 8 fp32->fp16 conversion jobs + the mu/lv interleave job.
// ---------------------------------------------------------------------------
#define NJOBS 8
#define SCATB 64
struct CvtJobs {
    const float* s[NJOBS];
    __half* d[NJOBS];
    int n4[NJOBS];
    int bstart[NJOBS + 2];       // offsets AFTER the SCATB scatter blocks
    const float* zmu; const float* zlv; __half* zo;
    const int* labels;
};

__global__ void __launch_bounds__(256)
k_prep(CvtJobs J) {
    int b = blockIdx.x;
    if (b < SCATB) {
        int i = b * 256 + threadIdx.x;
        if (i < BB) {
            int p = atomicAdd(&g_cursor[J.labels[i]], 1);
            g_perm[p] = i;
        }
        return;
    }
    b -= SCATB;
    if (b >= J.bstart[NJOBS]) {
        int lb = b - J.bstart[NJOBS];
#pragma unroll
        for (int it = 0; it < 4; it++) {
            int idx = lb * 1024 + it * 256 + threadIdx.x;
            if (idx < 4096) {
                float4 m = ((const float4*)J.zmu)[idx];
                float4 l = ((const float4*)J.zlv)[idx];
                int i0 = idx * 4;
                int k = i0 >> 6, j0 = i0 & 63;
                __half2* o = (__half2*)(J.zo + (size_t)k * 128 + 2 * j0);
                o[0] = __floats2half2_rn(m.x, l.x);
                o[1] = __floats2half2_rn(m.y, l.y);
                o[2] = __floats2half2_rn(m.z, l.z);
                o[3] = __floats2half2_rn(m.w, l.w);
            }
        }
        return;
    }
    int j = 0;
#pragma unroll
    for (int q = 1; q < NJOBS; q++)
        if (b >= J.bstart[q]) j = q;
    int lb = b - J.bstart[j];
    const float4* src = (const float4*)J.s[j];
    __half2* dst = (__half2*)J.d[j];
    int n4 = J.n4[j];
#pragma unroll
    for (int it = 0; it < 4; it++) {
        int idx = lb * 1024 + it * 256 + threadIdx.x;
        if (idx < n4) {
            float4 v = src[idx];
            dst[idx * 2 + 0] = __floats2half2_rn(v.x, v.y);
            dst[idx * 2 + 1] = __floats2half2_rn(v.z, v.w);
        }
    }
}

// ---------------------------------------------------------------------------
__device__ __forceinline__ void mma16(float* c, const uint32_t* a, const uint32_t* b) {
    asm volatile(
        "mma.sync.aligned.m16n8k16.row.col.f32.f16.f16.f32 "
        "{%0,%1,%2,%3}, {%4,%5,%6,%7}, {%8,%9}, {%0,%1,%2,%3};\n"
        : "+f"(c[0]), "+f"(c[1]), "+f"(c[2]), "+f"(c[3])
        : "r"(a[0]), "r"(a[1]), "r"(a[2]), "r"(a[3]), "r"(b[0]), "r"(b[1]));
}
__device__ __forceinline__ void ldsm4(uint32_t* r, uint32_t saddr) {
    asm volatile("ldmatrix.sync.aligned.m8n8.x4.shared.b16 {%0,%1,%2,%3}, [%4];"
                 : "=r"(r[0]), "=r"(r[1]), "=r"(r[2]), "=r"(r[3]) : "r"(saddr));
}
__device__ __forceinline__ void ldsm4t(uint32_t* r, uint32_t saddr) {
    asm volatile("ldmatrix.sync.aligned.m8n8.x4.trans.shared.b16 {%0,%1,%2,%3}, [%4];"
                 : "=r"(r[0]), "=r"(r[1]), "=r"(r[2]), "=r"(r[3]) : "r"(saddr));
}
__device__ __forceinline__ void cp16(uint32_t saddr, const void* g, int szbytes) {
    asm volatile("cp.async.cg.shared.global [%0], [%1], 16, %2;\n"
                 :: "r"(saddr), "l"(g), "r"(szbytes));
}
#define CP_COMMIT() asm volatile("cp.async.commit_group;\n")
#define CP_WAIT0()  asm volatile("cp.async.wait_group 0;\n")
#define CP_WAIT1()  asm volatile("cp.async.wait_group 1;\n")

// smem: 3 stages; A stage 64 rows x 80B = 5120B, B stage 32 rows x 272B
#define A_BUF 5120
#define B_BUF 8704
#define SB0   15360           // 3*A_BUF
#define SMEM_TOTAL 41472      // SB0 + 3*B_BUF  (static, < 48KB)

// ---------------------------------------------------------------------------
// MODE 0: bias+relu -> fp16 Out.
// MODE 2: interleaved mu/lv -> z = mu + exp(0.5 lv)*eps -> fp16 Out [.,64].
// MODE 3: bias only -> fp32 scatter to original rows.
// Tile 64x128x32, 4 warps (1M x 4N), warp 64x32. 3-stage pipeline.
// ---------------------------------------------------------------------------
template <int MODE, int K, int N>
__global__ void __launch_bounds__(128, 4)
k_hgemm(const __half* __restrict__ A, const __half* __restrict__ W,
        const float* __restrict__ bias, const float* __restrict__ bias2,
        const float* __restrict__ epsp, void* __restrict__ OutV,
        int unsharedF, int permAF) {
    if ((int)blockIdx.x >= g_numTiles) return;
    __shared__ __align__(16) __half smem_[SMEM_TOTAL / 2];
    uint32_t smb = (uint32_t)__cvta_generic_to_shared(smem_);

    int4 td = g_tiles[blockIdx.x];
    int rowStart = td.x, rows = td.y, cl = td.z;
    const __half* Wp = W + (unsharedF ? (size_t)cl * K * N : 0);
    const float* bp = bias + (unsharedF ? (size_t)cl * N : 0);
    int nb = blockIdx.y * 128;

    int tid = threadIdx.x;
    int warp = tid >> 5, lane = tid & 31;
    int wn = warp;                      // 4 warps span N; wm == 0
    int g = lane >> 2, tg = lane & 3;

    // staging coords: 2 A + 4 B 16B chunks per thread per 32-k block
    uint32_t aDst[2]; const __half* aSrc[2]; int aSz[2];
    uint32_t bDst[4]; const __half* bSrc[4];
#pragma unroll
    for (int i = 0; i < 2; i++) {
        int idx = tid + i * 128;          // 0..255 over A chunks
        int r = idx >> 2, ch = idx & 3;
        int ok = (r < rows);
        aSz[i] = ok ? 16 : 0;
        int ar = ok ? (permAF ? g_perm[rowStart + r] : rowStart + r) : 0;
        aDst[i] = smb + r * 80 + ch * 16;
        aSrc[i] = A + (size_t)ar * K + ch * 8;
    }
#pragma unroll
    for (int i = 0; i < 4; i++) {
        int idx = tid + i * 128;          // 0..511 over B chunks
        int kr = idx >> 4, cq = (idx & 15) << 3;
        bDst[i] = smb + SB0 + kr * 272 + cq * 2;
        bSrc[i] = Wp + (size_t)kr * N + nb + cq;
    }

    auto loadTile = [&](int blk, int s) {
        int ko = blk * 32;
#pragma unroll
        for (int i = 0; i < 2; i++) cp16(aDst[i] + s * A_BUF, aSrc[i] + ko, aSz[i]);
#pragma unroll
        for (int i = 0; i < 4; i++) cp16(bDst[i] + s * B_BUF, bSrc[i] + (size_t)ko * N, 16);
        CP_COMMIT();
    };

    uint32_t aF = smb + (uint32_t)((lane & 15) * 80 + ((lane >> 4) << 4));
    uint32_t bF = smb + SB0 +
        (uint32_t)((((lane >> 3) & 1) * 8 + (lane & 7)) * 272 + (wn * 32 + ((lane >> 4) << 3)) * 2);

    float acc[4][4][4];
#pragma unroll
    for (int a = 0; a < 4; a++)
#pragma unroll
        for (int b = 0; b < 4; b++)
#pragma unroll
            for (int d = 0; d < 4; d++) acc[a][b][d] = 0.f;

    const int nk = K / 32;
    loadTile(0, 0);
    if (nk > 1) loadTile(1, 1);

    for (int i = 0; i < nk; i++) {
        int s = i % 3;
        if (i + 1 < nk) { CP_WAIT1(); } else { CP_WAIT0(); }
        __syncthreads();
        if (i + 2 < nk) loadTile(i + 2, (i + 2) % 3);   // barrier made stage free

        uint32_t aB = aF + s * A_BUF, bB = bF + s * B_BUF;
#pragma unroll
        for (int ks = 0; ks < 2; ks++) {
            uint32_t af[4][4], bfr[2][4];
#pragma unroll
            for (int mt = 0; mt < 4; mt++)
                ldsm4(af[mt], aB + mt * (16 * 80) + ks * 32);
#pragma unroll
            for (int np = 0; np < 2; np++)
                ldsm4t(bfr[np], bB + ks * (16 * 272) + np * 32);
#pragma unroll
            for (int mt = 0; mt < 4; mt++)
#pragma unroll
                for (int nt = 0; nt < 4; nt++)
                    mma16(acc[mt][nt], af[mt], &bfr[nt >> 1][(nt & 1) * 2]);
        }
    }

    // epilogue
#pragma unroll
    for (int mt = 0; mt < 4; mt++) {
#pragma unroll
        for (int nt = 0; nt < 4; nt++) {
            int col = nb + wn * 32 + nt * 8 + 2 * tg;
            float bv0, bv1;
            if (MODE == 2) { int j = col >> 1; bv0 = bias[j]; bv1 = bias2[j]; }
            else { bv0 = bp[col]; bv1 = bp[col + 1]; }
#pragma unroll
            for (int h = 0; h < 2; h++) {
                int lr = mt * 16 + g + h * 8;
                if (lr < rows) {
                    int grow = rowStart + lr;
                    float v0 = acc[mt][nt][2 * h + 0] + bv0;
                    float v1 = acc[mt][nt][2 * h + 1] + bv1;
                    if (MODE == 0) {
                        __half2 hv = __floats2half2_rn(fmaxf(v0, 0.f), fmaxf(v1, 0.f));
                        *(__half2*)((__half*)OutV + (size_t)grow * N + col) = hv;
                    } else if (MODE == 2) {
                        int j = col >> 1;
                        int orig = g_perm[grow];
                        float e = epsp[(size_t)orig * 64 + j];
                        ((__half*)OutV)[(size_t)grow * 64 + j] =
                            __float2half(v0 + expf(0.5f * v1) * e);
                    } else {
                        int orig = g_perm[grow];
                        *(float2*)((float*)OutV + (size_t)orig * N + col) = make_float2(v0, v1);
                    }
                }
            }
        }
    }
}

// ---------------------------------------------------------------------------
extern "C" void kernel_launch(void* const* d_in, const int* in_sizes, int n_in,
                              void* d_out, int out_size) {
    const float* x      = (const float*)d_in[0];
    const int*   lbl    = (const int*)d_in[1];
    const float* eps    = (const float*)d_in[2];
    const float* enc_W0 = (const float*)d_in[3];
    const float* enc_b0 = (const float*)d_in[4];
    const float* enc_Wu = (const float*)d_in[5];
    const float* enc_bu = (const float*)d_in[6];
    const float* enc_W2 = (const float*)d_in[7];
    const float* enc_b2 = (const float*)d_in[8];
    const float* mu_W   = (const float*)d_in[9];
    const float* mu_b   = (const float*)d_in[10];
    const float* lv_W   = (const float*)d_in[11];
    const float* lv_b   = (const float*)d_in[12];
    const float* dWu0   = (const float*)d_in[13];
    const float* dbu0   = (const float*)d_in[14];
    const float* dW1    = (const float*)d_in[15];
    const float* db1    = (const float*)d_in[16];
    const float* dWu2   = (const float*)d_in[17];
    const float* dbu2   = (const float*)d_in[18];
    const float* fW     = (const float*)d_in[19];
    const float* fb     = (const float*)d_in[20];
    float* out = (float*)d_out;

    __half *bufA, *bufB, *xh, *wh, *whz;
    cudaGetSymbolAddress((void**)&bufA, g_bufA);
    cudaGetSymbolAddress((void**)&bufB, g_bufB);
    cudaGetSymbolAddress((void**)&xh,   g_xh);
    cudaGetSymbolAddress((void**)&wh,   g_wh);
    cudaGetSymbolAddress((void**)&whz,  g_whz);

    k_setup<<<1, 256>>>(lbl);

    // fused scatter + prepass (fp32->fp16 of x + 7 weights + z interleave)
    {
        CvtJobs J;
        const float* srcs[NJOBS] = {x, enc_W0, enc_Wu, enc_W2, dWu0, dW1, dWu2, fW};
        __half* dsts[NJOBS] = {xh, wh + O_EW0, wh + O_EWU, wh + O_EW2,
                               wh + O_DWU0, wh + O_DW1, wh + O_DWU2, wh + O_FW};
        int n4s[NJOBS] = {BB * 512 / 4, 524288 / 4, 4194304 / 4, 131072 / 4,
                          131072 / 4, 131072 / 4, 4194304 / 4, 4194304 / 4};
        int bs = 0;
        for (int j = 0; j < NJOBS; j++) {
            J.s[j] = srcs[j]; J.d[j] = dsts[j]; J.n4[j] = n4s[j];
            J.bstart[j] = bs;
            bs += (n4s[j] + 1023) / 1024;
        }
        J.bstart[NJOBS] = bs;
        bs += 4;
        J.bstart[NJOBS + 1] = bs;
        J.zmu = mu_W; J.zlv = lv_W; J.zo = whz;
        J.labels = lbl;
        k_prep<<<bs + SCATB, 256>>>(J);
    }

    // L1: xh(perm) @ enc_W0 [512->1024] relu
    k_hgemm<0, 512, 1024><<<dim3(MAXT, 8), 128>>>(xh, wh + O_EW0, enc_b0, nullptr, nullptr, bufA, 0, 1);
    // L2: H1 @ enc_Wu[c] [1024->512] relu
    k_hgemm<0, 1024, 512><<<dim3(MAXT, 4), 128>>>(bufA, wh + O_EWU, enc_bu, nullptr, nullptr, bufB, 1, 0);
    // L3: H2 @ enc_W2 [512->256] relu
    k_hgemm<0, 512, 256><<<dim3(MAXT, 2), 128>>>(bufB, wh + O_EW2, enc_b2, nullptr, nullptr, bufA, 0, 0);
    // L4: mu/lv heads (interleaved fp16 W) + reparameterize -> Z (fp16, 64 wide)
    k_hgemm<2, 256, 128><<<dim3(MAXT, 1), 128>>>(bufA, whz, mu_b, lv_b, eps, bufB, 0, 0);
    // L5: Z @ dec_Wu0[c] [64->256] relu
    k_hgemm<0, 64, 256><<<dim3(MAXT, 2), 128>>>(bufB, wh + O_DWU0, dbu0, nullptr, nullptr, bufA, 1, 0);
    // L6: D1 @ dec_W1 [256->512] relu
    k_hgemm<0, 256, 512><<<dim3(MAXT, 4), 128>>>(bufA, wh + O_DW1, db1, nullptr, nullptr, bufB, 0, 0);
    // L7: D2 @ dec_Wu2[c] [512->1024] relu
    k_hgemm<0, 512, 1024><<<dim3(MAXT, 8), 128>>>(bufB, wh + O_DWU2, dbu2, nullptr, nullptr, bufA, 1, 0);
    // L8: D3 @ fin_W[c] [1024->512], scatter to original rows (fp32 out)
    k_hgemm<3, 1024, 512><<<dim3(MAXT, 4), 128>>>(bufA, wh + O_FW, fb, nullptr, nullptr, out, 1, 0);
}